// round 3
// baseline (speedup 1.0000x reference)
#include <cuda_runtime.h>
#include <cstdint>

// Problem constants
constexpr int B_   = 8;
constexpr int H_   = 8;
constexpr int LQ_  = 1024;
constexpr int LM_  = 4096;
constexpr int DM_  = 512;
constexpr int DK_  = 64;
constexpr int TOPK_ = 32;

// Attention kernel tiling
constexpr int QT   = 8;     // queries per block == warps per block
constexpr int CK   = 256;   // key chunk cached in smem
constexpr int KROW = 68;    // padded K row (floats) -> conflict-free float4 LDS
constexpr int CAP  = 1024;  // per-row candidate buffer capacity

// Scratch (static device arrays: allocation-free)
__device__ float g_q[B_*H_*LQ_*DK_];   // 16 MB  [B,H,LQ,Dk]
__device__ float g_k[B_*H_*LM_*DK_];   // 64 MB  [B,H,LM,Dk]
__device__ float g_v[B_*H_*LM_*DK_];   // 64 MB  [B,H,LM,Dk]
__device__ float g_x[B_*LQ_*DM_];      // 16 MB  [B,LQ,DM] pre-output-proj

// ---------------- shared memory layout (4-byte units) ----------------------
constexpr int OFF_QS  = 0;                     // QT*DK floats (512)
constexpr int OFF_KS  = OFF_QS + QT*DK_;       // CK*KROW floats (17408); reused as cand bufs
constexpr int OFF_SC  = OFF_KS + CK*KROW;      // QT*LM uints (32768)
constexpr int OFF_SEL = OFF_SC + QT*LM_;       // QT*32 selu + QT*32 seli (512)
constexpr int SMEM_UNITS = OFF_SEL + 2*QT*32;
constexpr int SMEM_BYTES = SMEM_UNITS * 4;     // ~200 KB

// order-preserving float -> uint, and inverse
__device__ __forceinline__ unsigned ordu(float x) {
    unsigned u = __float_as_uint(x);
    return (u & 0x80000000u) ? ~u : (u | 0x80000000u);
}
__device__ __forceinline__ float iordu(unsigned v) {
    unsigned u = (v & 0x80000000u) ? (v ^ 0x80000000u) : ~v;
    return __uint_as_float(u);
}

// ---------------------------------------------------------------------------
// SGEMM: C = A[M,512] @ W[512,512]^T + bias   (torch Linear semantics)
// Two-level accumulation (numerics identical to round-2 passing version).
// ---------------------------------------------------------------------------
__global__ void __launch_bounds__(256, 1)
gemm512_kernel(const float* __restrict__ A, const float* __restrict__ W,
               const float* __restrict__ bias, float* __restrict__ C,
               int L, int head_major)
{
    __shared__ float As[8][128];
    __shared__ float Bs[8][128];

    const int t  = threadIdx.x;
    const int tx = t & 15;
    const int ty = t >> 4;
    const int m0 = blockIdx.x * 128;
    const int n0 = blockIdx.y * 128;
    const int lr = t >> 1;
    const int lc = (t & 1) << 2;

    const float* Ap = A + (size_t)(m0 + lr) * DM_ + lc;
    const float* Wp = W + (size_t)(n0 + lr) * DM_ + lc;

    float acc[8][8];
    #pragma unroll
    for (int i = 0; i < 8; i++)
        #pragma unroll
        for (int j = 0; j < 8; j++) acc[i][j] = 0.f;

    for (int k0 = 0; k0 < DM_; k0 += 8) {
        float4 av = *(const float4*)(Ap + k0);
        float4 wv = *(const float4*)(Wp + k0);
        __syncthreads();
        As[lc+0][lr] = av.x; As[lc+1][lr] = av.y; As[lc+2][lr] = av.z; As[lc+3][lr] = av.w;
        Bs[lc+0][lr] = wv.x; Bs[lc+1][lr] = wv.y; Bs[lc+2][lr] = wv.z; Bs[lc+3][lr] = wv.w;
        __syncthreads();

        float cacc[8][8];
        #pragma unroll
        for (int k = 0; k < 8; k++) {
            float a[8], bb[8];
            #pragma unroll
            for (int i = 0; i < 8; i++) a[i]  = As[k][ty*8 + i];
            #pragma unroll
            for (int j = 0; j < 8; j++) bb[j] = Bs[k][tx*8 + j];
            if (k == 0) {
                #pragma unroll
                for (int i = 0; i < 8; i++)
                    #pragma unroll
                    for (int j = 0; j < 8; j++)
                        cacc[i][j] = a[i] * bb[j];
            } else {
                #pragma unroll
                for (int i = 0; i < 8; i++)
                    #pragma unroll
                    for (int j = 0; j < 8; j++)
                        cacc[i][j] = fmaf(a[i], bb[j], cacc[i][j]);
            }
        }
        #pragma unroll
        for (int i = 0; i < 8; i++)
            #pragma unroll
            for (int j = 0; j < 8; j++)
                acc[i][j] += cacc[i][j];
    }

    #pragma unroll
    for (int i = 0; i < 8; i++) {
        int m  = m0 + ty*8 + i;
        int bb_ = m / L;
        int l   = m - bb_ * L;
        #pragma unroll
        for (int j = 0; j < 8; j++) {
            int n = n0 + tx*8 + j;
            float v = acc[i][j] + bias[n];
            if (head_major) {
                int hh = n >> 6, dk = n & 63;
                C[((size_t)(bb_*H_ + hh) * L + l) * DK_ + dk] = v;
            } else {
                C[(size_t)m * DM_ + n] = v;
            }
        }
    }
}

// ---------------------------------------------------------------------------
// Fused scores + EXACT top-32 (atomic-free per-warp 4-bit radix w/ register
// histograms + candidate compaction) + softmax + V gather.
// One block per (b, h, 8-query tile); 256 threads; warp w owns row w.
// ---------------------------------------------------------------------------
__global__ void __launch_bounds__(256, 1)
attn_topk_kernel(const float* __restrict__ gq, const float* __restrict__ gk,
                 const float* __restrict__ gv, float* __restrict__ gx)
{
    extern __shared__ float sm[];
    float*    qs   = sm + OFF_QS;
    float*    ks   = sm + OFF_KS;          // score phase; reused as cand bufs
    unsigned* scU  = (unsigned*)(sm + OFF_SC);
    unsigned* selB = (unsigned*)(sm + OFF_SEL);

    const int t    = threadIdx.x;
    const int lane = t & 31;
    const int w    = t >> 5;               // warp id == row id
    const int qt0  = blockIdx.x * QT;
    const int h    = blockIdx.y;
    const int b    = blockIdx.z;
    const unsigned FULL = 0xffffffffu;
    const unsigned lt   = (1u << lane) - 1u;

    // ---- load Q tile (8x64 fp32) ----
    const float* qbase = gq + ((size_t)(b*H_ + h) * LQ_ + qt0) * DK_;
    if (t < QT*DK_/4) ((float4*)qs)[t] = ((const float4*)qbase)[t];
    __syncthreads();

    // ---- scores: stream K in 256-key chunks, thread-per-key (numerics
    //      identical to the passing round-2 kernel; stored as ordu uint) ----
    const float* kbase = gk + (size_t)(b*H_ + h) * LM_ * DK_;
    for (int c0 = 0; c0 < LM_; c0 += CK) {
        for (int i = t; i < CK*(DK_/4); i += 256) {
            int row = i >> 4, col = i & 15;
            float4 v4 = ((const float4*)(kbase + (size_t)(c0 + row) * DK_))[col];
            *(float4*)(ks + row*KROW + col*4) = v4;
        }
        __syncthreads();

        float acc[QT];
        #pragma unroll
        for (int qi = 0; qi < QT; qi++) acc[qi] = 0.f;
        const float4* krow = (const float4*)(ks + t*KROW);
        #pragma unroll
        for (int d4 = 0; d4 < DK_/4; d4++) {
            float4 kv = krow[d4];
            #pragma unroll
            for (int qi = 0; qi < QT; qi++) {
                float4 qv = ((const float4*)(qs + qi*DK_))[d4];
                acc[qi] += kv.x*qv.x + kv.y*qv.y + kv.z*qv.z + kv.w*qv.w;
            }
        }
        #pragma unroll
        for (int qi = 0; qi < QT; qi++)
            scU[qi*LM_ + c0 + t] = ordu(acc[qi] * 0.125f);   // 1/sqrt(64)
        __syncthreads();
    }
    // NOTE: ks region is now free; reuse as candidate buffers below.

    // ---- per-warp exact top-32 on row w ----
    unsigned* row   = scU + w*LM_;
    unsigned* candU = (unsigned*)ks + (size_t)w * CAP;
    int*      candI = (int*)ks + (size_t)QT*CAP + (size_t)w * CAP;
    unsigned* selu  = selB + w*32;
    int*      seli  = (int*)(selB + QT*32) + w*32;

    unsigned prefix = 0;
    int kneed  = TOPK_;
    int selCnt = 0, candC = 0;
    const unsigned* buf = row;
    int  n = LM_;
    int  inCand = 0;

    #pragma unroll 1
    for (int p = 0; p < 8; p++) {
        const int shift = 28 - 4*p;
        int cnt[16];
        #pragma unroll
        for (int bb = 0; bb < 16; bb++) cnt[bb] = 0;

        for (int i = lane; i < n; i += 32) {
            unsigned u = buf[i];
            // shift+4 == 32 at p==0: SASS SHR clamps -> 0 == prefix(0) -> true
            bool act = (p == 0) | ((u >> (shift + 4)) == prefix);
            unsigned d = (u >> shift) & 15u;
            #pragma unroll
            for (int bb = 0; bb < 16; bb++)
                cnt[bb] += (act && d == (unsigned)bb) ? 1 : 0;
        }
        // warp-reduce all 16 counters
        #pragma unroll
        for (int bb = 0; bb < 16; bb++) {
            int s = cnt[bb];
            #pragma unroll
            for (int off = 16; off; off >>= 1)
                s += __shfl_xor_sync(FULL, s, off);
            cnt[bb] = s;
        }
        // pick largest bin with suffix >= kneed
        int run = 0, bin = 15;
        #pragma unroll
        for (int bb = 15; bb >= 0; bb--) {
            if (run + cnt[bb] >= kneed) { bin = bb; break; }
            run += cnt[bb];
        }
        prefix = (prefix << 4) | (unsigned)bin;
        kneed -= run;                    // 'run' strictly-above elems are locked in
        int C = cnt[bin];

        if (p == 3) {
            // emit the definite winners (top16 > prefix16); compact the tie band
            int doCompact = (C <= CAP);
            for (int i0 = 0; i0 < LM_; i0 += 32) {
                int i = i0 + lane;
                unsigned u = row[i];
                bool ab = (u >> 16) > prefix;
                bool eq = doCompact && ((u >> 16) == prefix);
                unsigned mA = __ballot_sync(FULL, ab);
                unsigned mE = __ballot_sync(FULL, eq);
                if (ab) { int pos = selCnt + __popc(mA & lt); selu[pos] = u; seli[pos] = i; }
                if (eq) { int pos = candC  + __popc(mE & lt); candU[pos] = u; candI[pos] = i; }
                selCnt += __popc(mA);
                candC  += __popc(mE);
            }
            if (doCompact) { buf = candU; n = candC; inCand = 1; }
            // else: passes 5-8 + final scan run over the full row (rare fallback)
        }
    }

    // ---- final selection: remaining strict-above + 'kneed' exact-equals ----
    {
        const unsigned p16 = prefix >> 16;
        int eqTaken = 0;
        for (int i0 = 0; i0 < n; i0 += 32) {
            int i = i0 + lane;
            unsigned u = (i < n) ? buf[i] : 0u;
            bool ab = (i < n) && (u > prefix) && ((u >> 16) == p16);
            bool eq = (i < n) && (u == prefix);
            unsigned mA = __ballot_sync(FULL, ab);
            unsigned mE = __ballot_sync(FULL, eq);
            if (ab) {
                int pos = selCnt + __popc(mA & lt);
                selu[pos] = u; seli[pos] = inCand ? candI[i] : i;
            }
            if (eq) {
                int rk = eqTaken + __popc(mE & lt);
                if (rk < kneed) {
                    int pos = TOPK_ - kneed + rk;
                    selu[pos] = u; seli[pos] = inCand ? candI[i] : i;
                }
            }
            selCnt  += __popc(mA);
            eqTaken += __popc(mE);
        }
    }
    __syncwarp();

    // ---- softmax over the 32 selected scores (one per lane) ----
    float v  = iordu(selu[lane]);
    int   ki = seli[lane];
    float mx = v;
    #pragma unroll
    for (int off = 16; off; off >>= 1)
        mx = fmaxf(mx, __shfl_xor_sync(FULL, mx, off));
    float e = __expf(v - mx);
    float s = e;
    #pragma unroll
    for (int off = 16; off; off >>= 1)
        s += __shfl_xor_sync(FULL, s, off);
    float wgt = e / s;

    // ---- weighted V gather: 32 rows x 64 dims, coalesced 128B halves ----
    const float* vbase = gv + (size_t)(b*H_ + h) * LM_ * DK_;
    float a0 = 0.f, a1 = 0.f;
    #pragma unroll 4
    for (int it = 0; it < TOPK_; it++) {
        float wi = __shfl_sync(FULL, wgt, it);
        int   kk = __shfl_sync(FULL, ki,  it);
        const float* vr = vbase + (size_t)kk * DK_;
        a0 = fmaf(wi, vr[lane],      a0);
        a1 = fmaf(wi, vr[lane + 32], a1);
    }
    float* orow = gx + ((size_t)b * LQ_ + (qt0 + w)) * DM_ + h*DK_;
    orow[lane]      = a0;
    orow[lane + 32] = a1;
}

// ---------------------------------------------------------------------------
extern "C" void kernel_launch(void* const* d_in, const int* in_sizes, int n_in,
                              void* d_out, int out_size)
{
    const float* query = (const float*)d_in[0];
    const float* key   = (const float*)d_in[1];
    const float* value = (const float*)d_in[2];
    const float* Wq    = (const float*)d_in[3];
    const float* bq    = (const float*)d_in[4];
    const float* Wk    = (const float*)d_in[5];
    const float* bk    = (const float*)d_in[6];
    const float* Wv    = (const float*)d_in[7];
    const float* bv    = (const float*)d_in[8];
    const float* Wo    = (const float*)d_in[9];
    const float* bo    = (const float*)d_in[10];
    float* out = (float*)d_out;

    float *pq, *pk, *pv, *px;
    cudaGetSymbolAddress((void**)&pq, g_q);
    cudaGetSymbolAddress((void**)&pk, g_k);
    cudaGetSymbolAddress((void**)&pv, g_v);
    cudaGetSymbolAddress((void**)&px, g_x);

    cudaFuncSetAttribute(attn_topk_kernel,
                         cudaFuncAttributeMaxDynamicSharedMemorySize, SMEM_BYTES);

    // projections into head-major scratch
    gemm512_kernel<<<dim3(B_*LQ_/128, DM_/128), 256>>>(query, Wq, bq, pq, LQ_, 1);
    gemm512_kernel<<<dim3(B_*LM_/128, DM_/128), 256>>>(key,   Wk, bk, pk, LM_, 1);
    gemm512_kernel<<<dim3(B_*LM_/128, DM_/128), 256>>>(value, Wv, bv, pv, LM_, 1);

    // fused scores + topk + softmax + gather
    attn_topk_kernel<<<dim3(LQ_/QT, H_, B_), 256, SMEM_BYTES>>>(pq, pk, pv, px);

    // output projection (plain row-major)
    gemm512_kernel<<<dim3(B_*LQ_/128, DM_/128), 256>>>(px, Wo, bo, out, LQ_, 0);
}

// round 4
// speedup vs baseline: 2.2822x; 2.2822x over previous
#include <cuda_runtime.h>
#include <cstdint>

// Problem constants
constexpr int B_   = 8;
constexpr int H_   = 8;
constexpr int LQ_  = 1024;
constexpr int LM_  = 4096;
constexpr int DM_  = 512;
constexpr int DK_  = 64;
constexpr int TOPK_ = 32;

// Attention kernel tiling
constexpr int QT   = 8;     // queries per block == warps per block
constexpr int CK   = 256;   // key chunk cached in smem

// Scratch (static device arrays: allocation-free)
__device__ float g_q[B_*H_*LQ_*DK_];   // 16 MB  [B,H,LQ,Dk]
__device__ float g_k[B_*H_*LM_*DK_];   // 64 MB  [B,H,LM,Dk]
__device__ float g_v[B_*H_*LM_*DK_];   // 64 MB  [B,H,LM,Dk]
__device__ float g_x[B_*LQ_*DM_];      // 16 MB  [B,LQ,DM] pre-output-proj

// ---------------- attention smem layout (floats) ---------------------------
constexpr int OFF_QS  = 0;                 // 512  : Q tile 8x64
constexpr int OFF_KS  = OFF_QS + QT*DK_;   // 16384: K chunk 256x64, xor-swizzled float4
constexpr int OFF_SCC = OFF_KS + CK*DK_;   // 2048 : score staging 8x256 (ordu uints)
constexpr int SMEM_FLOATS = OFF_SCC + QT*CK;
constexpr int SMEM_BYTES  = SMEM_FLOATS * 4;   // 75776 B -> 2 blocks/SM

// order-preserving float -> uint, and inverse
__device__ __forceinline__ unsigned ordu(float x) {
    unsigned u = __float_as_uint(x);
    return (u & 0x80000000u) ? ~u : (u | 0x80000000u);
}
__device__ __forceinline__ float iordu(unsigned v) {
    unsigned u = (v & 0x80000000u) ? (v ^ 0x80000000u) : ~v;
    return __uint_as_float(u);
}

// ---------------------------------------------------------------------------
// SGEMM: C = A[M,512] @ W[512,512]^T + bias (torch Linear semantics).
// Double-buffered smem pipeline; per-thread FP arithmetic order IDENTICAL to
// the round-2 passing version (two-level accumulation).
// grid: (M/128, 4), block: 256 threads, 8x8 per thread.
// ---------------------------------------------------------------------------
__global__ void __launch_bounds__(256, 1)
gemm512_kernel(const float* __restrict__ A, const float* __restrict__ W,
               const float* __restrict__ bias, float* __restrict__ C,
               int L, int head_major)
{
    __shared__ float As[2][8][128];
    __shared__ float Bs[2][8][128];

    const int t  = threadIdx.x;
    const int tx = t & 15;
    const int ty = t >> 4;
    const int m0 = blockIdx.x * 128;
    const int n0 = blockIdx.y * 128;
    const int lr = t >> 1;
    const int lc = (t & 1) << 2;

    const float* Ap = A + (size_t)(m0 + lr) * DM_ + lc;
    const float* Wp = W + (size_t)(n0 + lr) * DM_ + lc;

    // prologue: stage k-tile 0 into buffer 0
    float4 av = *(const float4*)(Ap);
    float4 wv = *(const float4*)(Wp);
    As[0][lc+0][lr] = av.x; As[0][lc+1][lr] = av.y; As[0][lc+2][lr] = av.z; As[0][lc+3][lr] = av.w;
    Bs[0][lc+0][lr] = wv.x; Bs[0][lc+1][lr] = wv.y; Bs[0][lc+2][lr] = wv.z; Bs[0][lc+3][lr] = wv.w;
    __syncthreads();

    float acc[8][8];
    #pragma unroll
    for (int i = 0; i < 8; i++)
        #pragma unroll
        for (int j = 0; j < 8; j++) acc[i][j] = 0.f;

    #pragma unroll 1
    for (int k0 = 0; k0 < DM_; k0 += 8) {
        const int  p    = (k0 >> 3) & 1;
        const bool more = (k0 + 8) < DM_;
        if (more) {
            av = *(const float4*)(Ap + k0 + 8);
            wv = *(const float4*)(Wp + k0 + 8);
        }

        float cacc[8][8];
        #pragma unroll
        for (int k = 0; k < 8; k++) {
            float a[8], bb[8];
            #pragma unroll
            for (int i = 0; i < 8; i++) a[i]  = As[p][k][ty*8 + i];
            #pragma unroll
            for (int j = 0; j < 8; j++) bb[j] = Bs[p][k][tx*8 + j];
            if (k == 0) {
                #pragma unroll
                for (int i = 0; i < 8; i++)
                    #pragma unroll
                    for (int j = 0; j < 8; j++)
                        cacc[i][j] = a[i] * bb[j];
            } else {
                #pragma unroll
                for (int i = 0; i < 8; i++)
                    #pragma unroll
                    for (int j = 0; j < 8; j++)
                        cacc[i][j] = fmaf(a[i], bb[j], cacc[i][j]);
            }
        }
        #pragma unroll
        for (int i = 0; i < 8; i++)
            #pragma unroll
            for (int j = 0; j < 8; j++)
                acc[i][j] += cacc[i][j];

        if (more) {
            const int q = p ^ 1;
            As[q][lc+0][lr] = av.x; As[q][lc+1][lr] = av.y; As[q][lc+2][lr] = av.z; As[q][lc+3][lr] = av.w;
            Bs[q][lc+0][lr] = wv.x; Bs[q][lc+1][lr] = wv.y; Bs[q][lc+2][lr] = wv.z; Bs[q][lc+3][lr] = wv.w;
        }
        __syncthreads();
    }

    #pragma unroll
    for (int i = 0; i < 8; i++) {
        int m  = m0 + ty*8 + i;
        int bb_ = m / L;
        int l   = m - bb_ * L;
        #pragma unroll
        for (int j = 0; j < 8; j++) {
            int n = n0 + tx*8 + j;
            float v = acc[i][j] + bias[n];
            if (head_major) {
                int hh = n >> 6, dk = n & 63;
                C[((size_t)(bb_*H_ + hh) * L + l) * DK_ + dk] = v;
            } else {
                C[(size_t)m * DM_ + n] = v;
            }
        }
    }
}

// ---------------------------------------------------------------------------
// Fused scores + EXACT top-32 (running register top-k with threshold
// short-circuit + REDUX) + softmax + V gather.
// One block per (b, h, 8-query tile); 256 threads; warp w owns row w.
// Score arithmetic identical to the round-2 passing kernel.
// ---------------------------------------------------------------------------
__global__ void __launch_bounds__(256, 2)
attn_topk_kernel(const float* __restrict__ gq, const float* __restrict__ gk,
                 const float* __restrict__ gv, float* __restrict__ gx)
{
    extern __shared__ float sm[];
    float*    qs  = sm + OFF_QS;
    float*    ks  = sm + OFF_KS;                 // xor-swizzled float4 tile
    unsigned* scC = (unsigned*)(sm + OFF_SCC);   // 8 x 256 ordu scores

    const int t    = threadIdx.x;
    const int lane = t & 31;
    const int w    = t >> 5;              // warp id == query row id
    const int qt0  = blockIdx.x * QT;
    const int h    = blockIdx.y;
    const int b    = blockIdx.z;
    const unsigned FULL = 0xffffffffu;

    // ---- load Q tile (8x64 fp32) ----
    const float* qbase = gq + ((size_t)(b*H_ + h) * LQ_ + qt0) * DK_;
    if (t < QT*DK_/4) ((float4*)qs)[t] = ((const float4*)qbase)[t];

    const float* kbase = gk + (size_t)(b*H_ + h) * LM_ * DK_;

    // running top-32 state: one (val, idx) per lane; m = warp-uniform min
    unsigned bval = 0u;
    int      bidx = 0;
    unsigned m    = 0u;

    #pragma unroll 1
    for (int c0 = 0; c0 < LM_; c0 += CK) {
        __syncthreads();  // prev chunk's select done before scC overwrite path

        // ---- stage K chunk (256 x 64) with XOR swizzle: conflict-free ----
        #pragma unroll
        for (int i = t; i < CK*16; i += 256) {
            int row = i >> 4, col = i & 15;
            float4 v4 = ((const float4*)(kbase + (size_t)(c0 + row) * DK_))[col];
            ((float4*)ks)[(row << 4) | (col ^ (row & 15))] = v4;
        }
        __syncthreads();

        // ---- scores: thread t owns key c0+t, 8 queries (same FMA order) ----
        float acc[QT];
        #pragma unroll
        for (int qi = 0; qi < QT; qi++) acc[qi] = 0.f;
        const float4* ks4 = (const float4*)ks;
        #pragma unroll
        for (int d4 = 0; d4 < DK_/4; d4++) {
            float4 kv = ks4[(t << 4) | (d4 ^ (t & 15))];
            #pragma unroll
            for (int qi = 0; qi < QT; qi++) {
                float4 qv = ((const float4*)(qs + qi*DK_))[d4];
                acc[qi] += kv.x*qv.x + kv.y*qv.y + kv.z*qv.z + kv.w*qv.w;
            }
        }
        #pragma unroll
        for (int qi = 0; qi < QT; qi++)
            scC[qi*CK + t] = ordu(acc[qi] * 0.125f);   // 1/sqrt(64)
        __syncthreads();

        // ---- select: warp w updates its running top-32 over this segment ----
        #pragma unroll 1
        for (int bb = 0; bb < CK/32; bb++) {
            const int i0 = c0 + bb*32;
            unsigned u = scC[w*CK + bb*32 + lane];

            if (c0 == 0 && bb == 0) {       // initial fill: first 32 elements
                bval = u; bidx = lane;
                m = __reduce_min_sync(FULL, bval);
                continue;
            }

            unsigned hit = __ballot_sync(FULL, u > m);
            while (hit) {                    // warp-uniform rare path
                int s = __ffs(hit) - 1; hit &= hit - 1;
                unsigned uc = __shfl_sync(FULL, u, s);
                if (uc > m) {                // recheck vs updated m (uniform)
                    int ic = i0 + s;
                    unsigned em = __ballot_sync(FULL, bval == m);
                    int el;
                    if (__popc(em) > 1) {
                        // tie on min value: evict the LARGER index (jax keeps lower)
                        int cb = ((em >> lane) & 1) ? bidx : -1;
                        int mx = __reduce_max_sync(FULL, cb);
                        el = __ffs(__ballot_sync(FULL, (bval == m) && (bidx == mx))) - 1;
                    } else {
                        el = __ffs(em) - 1;
                    }
                    if (lane == el) { bval = uc; bidx = ic; }
                    m = __reduce_min_sync(FULL, bval);
                }
            }
        }
    }

    // ---- softmax over the 32 selected scores (one per lane) ----
    float v  = iordu(bval);
    float mx = v;
    #pragma unroll
    for (int off = 16; off; off >>= 1)
        mx = fmaxf(mx, __shfl_xor_sync(FULL, mx, off));
    float e = __expf(v - mx);
    float s = e;
    #pragma unroll
    for (int off = 16; off; off >>= 1)
        s += __shfl_xor_sync(FULL, s, off);
    float wgt = e / s;

    // ---- weighted V gather: 32 rows x 64 dims, coalesced 128B halves ----
    const float* vbase = gv + (size_t)(b*H_ + h) * LM_ * DK_;
    float a0 = 0.f, a1 = 0.f;
    #pragma unroll 4
    for (int it = 0; it < TOPK_; it++) {
        float wi = __shfl_sync(FULL, wgt, it);
        int   kk = __shfl_sync(FULL, bidx, it);
        const float* vr = vbase + (size_t)kk * DK_;
        a0 = fmaf(wi, vr[lane],      a0);
        a1 = fmaf(wi, vr[lane + 32], a1);
    }
    float* orow = gx + ((size_t)b * LQ_ + (qt0 + w)) * DM_ + h*DK_;
    orow[lane]      = a0;
    orow[lane + 32] = a1;
}

// ---------------------------------------------------------------------------
extern "C" void kernel_launch(void* const* d_in, const int* in_sizes, int n_in,
                              void* d_out, int out_size)
{
    const float* query = (const float*)d_in[0];
    const float* key   = (const float*)d_in[1];
    const float* value = (const float*)d_in[2];
    const float* Wq    = (const float*)d_in[3];
    const float* bq    = (const float*)d_in[4];
    const float* Wk    = (const float*)d_in[5];
    const float* bk    = (const float*)d_in[6];
    const float* Wv    = (const float*)d_in[7];
    const float* bv    = (const float*)d_in[8];
    const float* Wo    = (const float*)d_in[9];
    const float* bo    = (const float*)d_in[10];
    float* out = (float*)d_out;

    float *pq, *pk, *pv, *px;
    cudaGetSymbolAddress((void**)&pq, g_q);
    cudaGetSymbolAddress((void**)&pk, g_k);
    cudaGetSymbolAddress((void**)&pv, g_v);
    cudaGetSymbolAddress((void**)&px, g_x);

    cudaFuncSetAttribute(attn_topk_kernel,
                         cudaFuncAttributeMaxDynamicSharedMemorySize, SMEM_BYTES);

    // projections into head-major scratch
    gemm512_kernel<<<dim3(B_*LQ_/128, DM_/128), 256>>>(query, Wq, bq, pq, LQ_, 1);
    gemm512_kernel<<<dim3(B_*LM_/128, DM_/128), 256>>>(key,   Wk, bk, pk, LM_, 1);
    gemm512_kernel<<<dim3(B_*LM_/128, DM_/128), 256>>>(value, Wv, bv, pv, LM_, 1);

    // fused scores + topk + softmax + gather
    attn_topk_kernel<<<dim3(LQ_/QT, H_, B_), 256, SMEM_BYTES>>>(pq, pk, pv, px);

    // output projection (plain row-major)
    gemm512_kernel<<<dim3(B_*LQ_/128, DM_/128), 256>>>(px, Wo, bo, out, LQ_, 0);
}

// round 5
// speedup vs baseline: 2.3964x; 1.0501x over previous
#include <cuda_runtime.h>
#include <cstdint>

// Problem constants
constexpr int B_   = 8;
constexpr int H_   = 8;
constexpr int LQ_  = 1024;
constexpr int LM_  = 4096;
constexpr int DM_  = 512;
constexpr int DK_  = 64;
constexpr int TOPK_ = 32;

// Attention kernel tiling
constexpr int QT   = 8;     // queries per block == warps per block
constexpr int CK   = 128;   // key chunk cached in smem (32 KB)

// Scratch (static device arrays: allocation-free)
__device__ float g_q[B_*H_*LQ_*DK_];   // 16 MB  [B,H,LQ,Dk]
__device__ float g_k[B_*H_*LM_*DK_];   // 64 MB  [B,H,LM,Dk]
__device__ float g_v[B_*H_*LM_*DK_];   // 64 MB  [B,H,LM,Dk]
__device__ float g_x[B_*LQ_*DM_];      // 16 MB  [B,LQ,DM] pre-output-proj

// ---------------- attention smem layout (floats) ---------------------------
constexpr int OFF_QS  = 0;                 // 512  : Q tile 8x64
constexpr int OFF_KS  = OFF_QS + QT*DK_;   // 8192 : K chunk 128x64, xor-swizzled float4
constexpr int OFF_SCC = OFF_KS + CK*DK_;   // 1024 : score staging 8x128 (ordu uints)
constexpr int SMEM_FLOATS = OFF_SCC + QT*CK;
constexpr int SMEM_BYTES  = SMEM_FLOATS * 4;   // 38912 B -> 3 blocks/SM (smem)

// order-preserving float -> uint, and inverse
__device__ __forceinline__ unsigned ordu(float x) {
    unsigned u = __float_as_uint(x);
    return (u & 0x80000000u) ? ~u : (u | 0x80000000u);
}
__device__ __forceinline__ float iordu(unsigned v) {
    unsigned u = (v & 0x80000000u) ? (v ^ 0x80000000u) : ~v;
    return __uint_as_float(u);
}

// ---------------------------------------------------------------------------
// SGEMM: C = A[M,512] @ W[512,512]^T + bias (torch Linear semantics).
// Double-buffered smem pipeline; per-thread FP arithmetic order IDENTICAL to
// the round-2 passing version (two-level accumulation). UNCHANGED this round.
// grid: (M/128, 4), block: 256 threads, 8x8 per thread.
// ---------------------------------------------------------------------------
__global__ void __launch_bounds__(256, 1)
gemm512_kernel(const float* __restrict__ A, const float* __restrict__ W,
               const float* __restrict__ bias, float* __restrict__ C,
               int L, int head_major)
{
    __shared__ float As[2][8][128];
    __shared__ float Bs[2][8][128];

    const int t  = threadIdx.x;
    const int tx = t & 15;
    const int ty = t >> 4;
    const int m0 = blockIdx.x * 128;
    const int n0 = blockIdx.y * 128;
    const int lr = t >> 1;
    const int lc = (t & 1) << 2;

    const float* Ap = A + (size_t)(m0 + lr) * DM_ + lc;
    const float* Wp = W + (size_t)(n0 + lr) * DM_ + lc;

    float4 av = *(const float4*)(Ap);
    float4 wv = *(const float4*)(Wp);
    As[0][lc+0][lr] = av.x; As[0][lc+1][lr] = av.y; As[0][lc+2][lr] = av.z; As[0][lc+3][lr] = av.w;
    Bs[0][lc+0][lr] = wv.x; Bs[0][lc+1][lr] = wv.y; Bs[0][lc+2][lr] = wv.z; Bs[0][lc+3][lr] = wv.w;
    __syncthreads();

    float acc[8][8];
    #pragma unroll
    for (int i = 0; i < 8; i++)
        #pragma unroll
        for (int j = 0; j < 8; j++) acc[i][j] = 0.f;

    #pragma unroll 1
    for (int k0 = 0; k0 < DM_; k0 += 8) {
        const int  p    = (k0 >> 3) & 1;
        const bool more = (k0 + 8) < DM_;
        if (more) {
            av = *(const float4*)(Ap + k0 + 8);
            wv = *(const float4*)(Wp + k0 + 8);
        }

        float cacc[8][8];
        #pragma unroll
        for (int k = 0; k < 8; k++) {
            float a[8], bb[8];
            #pragma unroll
            for (int i = 0; i < 8; i++) a[i]  = As[p][k][ty*8 + i];
            #pragma unroll
            for (int j = 0; j < 8; j++) bb[j] = Bs[p][k][tx*8 + j];
            if (k == 0) {
                #pragma unroll
                for (int i = 0; i < 8; i++)
                    #pragma unroll
                    for (int j = 0; j < 8; j++)
                        cacc[i][j] = a[i] * bb[j];
            } else {
                #pragma unroll
                for (int i = 0; i < 8; i++)
                    #pragma unroll
                    for (int j = 0; j < 8; j++)
                        cacc[i][j] = fmaf(a[i], bb[j], cacc[i][j]);
            }
        }
        #pragma unroll
        for (int i = 0; i < 8; i++)
            #pragma unroll
            for (int j = 0; j < 8; j++)
                acc[i][j] += cacc[i][j];

        if (more) {
            const int q = p ^ 1;
            As[q][lc+0][lr] = av.x; As[q][lc+1][lr] = av.y; As[q][lc+2][lr] = av.z; As[q][lc+3][lr] = av.w;
            Bs[q][lc+0][lr] = wv.x; Bs[q][lc+1][lr] = wv.y; Bs[q][lc+2][lr] = wv.z; Bs[q][lc+3][lr] = wv.w;
        }
        __syncthreads();
    }

    #pragma unroll
    for (int i = 0; i < 8; i++) {
        int m  = m0 + ty*8 + i;
        int bb_ = m / L;
        int l   = m - bb_ * L;
        #pragma unroll
        for (int j = 0; j < 8; j++) {
            int n = n0 + tx*8 + j;
            float v = acc[i][j] + bias[n];
            if (head_major) {
                int hh = n >> 6, dk = n & 63;
                C[((size_t)(bb_*H_ + hh) * L + l) * DK_ + dk] = v;
            } else {
                C[(size_t)m * DM_ + n] = v;
            }
        }
    }
}

// ---------------------------------------------------------------------------
// Fused scores + EXACT top-32 (running register top-k with threshold
// short-circuit + REDUX) + softmax + V gather.
// One block per (b, h, 8-query tile); 256 threads; warp w owns row w.
// Score arithmetic and global selection order bit-identical to round 4
// (CK change does not alter per-key expression or batch visit order).
// ---------------------------------------------------------------------------
__global__ void __launch_bounds__(256, 3)
attn_topk_kernel(const float* __restrict__ gq, const float* __restrict__ gk,
                 const float* __restrict__ gv, float* __restrict__ gx)
{
    extern __shared__ float sm[];
    float*    qs  = sm + OFF_QS;
    float*    ks  = sm + OFF_KS;                 // xor-swizzled float4 tile
    unsigned* scC = (unsigned*)(sm + OFF_SCC);   // 8 x CK ordu scores

    const int t    = threadIdx.x;
    const int lane = t & 31;
    const int w    = t >> 5;              // warp id == query row id
    const int qt0  = blockIdx.x * QT;
    const int h    = blockIdx.y;
    const int b    = blockIdx.z;
    const unsigned FULL = 0xffffffffu;

    // ---- load Q tile (8x64 fp32) ----
    const float* qbase = gq + ((size_t)(b*H_ + h) * LQ_ + qt0) * DK_;
    if (t < QT*DK_/4) ((float4*)qs)[t] = ((const float4*)qbase)[t];

    const float* kbase = gk + (size_t)(b*H_ + h) * LM_ * DK_;
    const int kt = t >> 1;                 // key owned in score phase (2 thr/key)
    const int kd = (t & 1) << 3;           // which half of d4 range this thread... (unused)

    // running top-32 state: one (val, idx) per lane; m = warp-uniform min
    unsigned bval = 0u;
    int      bidx = 0;
    unsigned m    = 0u;

    #pragma unroll 1
    for (int c0 = 0; c0 < LM_; c0 += CK) {
        __syncthreads();  // prev chunk's select done before scC/ks overwrite

        // ---- stage K chunk (CK x 64) with XOR swizzle: conflict-free ----
        #pragma unroll
        for (int i = t; i < CK*16; i += 256) {
            int row = i >> 4, col = i & 15;
            float4 v4 = ((const float4*)(kbase + (size_t)(c0 + row) * DK_))[col];
            ((float4*)ks)[(row << 4) | (col ^ (row & 15))] = v4;
        }
        __syncthreads();

        // ---- scores: threads 0..CK-1 own key c0+t (same FMA order) ----
        if (t < CK) {
            float acc[QT];
            #pragma unroll
            for (int qi = 0; qi < QT; qi++) acc[qi] = 0.f;
            const float4* ks4 = (const float4*)ks;
            #pragma unroll
            for (int d4 = 0; d4 < DK_/4; d4++) {
                float4 kv = ks4[(t << 4) | (d4 ^ (t & 15))];
                #pragma unroll
                for (int qi = 0; qi < QT; qi++) {
                    float4 qv = ((const float4*)(qs + qi*DK_))[d4];
                    acc[qi] += kv.x*qv.x + kv.y*qv.y + kv.z*qv.z + kv.w*qv.w;
                }
            }
            #pragma unroll
            for (int qi = 0; qi < QT; qi++)
                scC[qi*CK + t] = ordu(acc[qi] * 0.125f);   // 1/sqrt(64)
        }
        __syncthreads();

        // ---- select: warp w updates its running top-32 over this segment ----
        #pragma unroll 1
        for (int bb = 0; bb < CK/32; bb++) {
            const int i0 = c0 + bb*32;
            unsigned u = scC[w*CK + bb*32 + lane];

            if (c0 == 0 && bb == 0) {       // initial fill: first 32 elements
                bval = u; bidx = lane;
                m = __reduce_min_sync(FULL, bval);
                continue;
            }

            unsigned hit = __ballot_sync(FULL, u > m);
            while (hit) {                    // warp-uniform rare path
                int s = __ffs(hit) - 1; hit &= hit - 1;
                unsigned uc = __shfl_sync(FULL, u, s);
                if (uc > m) {                // recheck vs updated m (uniform)
                    int ic = i0 + s;
                    unsigned em = __ballot_sync(FULL, bval == m);
                    int el;
                    if (__popc(em) > 1) {
                        // tie on min value: evict the LARGER index (jax keeps lower)
                        int cb = ((em >> lane) & 1) ? bidx : -1;
                        int mx = __reduce_max_sync(FULL, cb);
                        el = __ffs(__ballot_sync(FULL, (bval == m) && (bidx == mx))) - 1;
                    } else {
                        el = __ffs(em) - 1;
                    }
                    if (lane == el) { bval = uc; bidx = ic; }
                    m = __reduce_min_sync(FULL, bval);
                }
            }
        }
    }

    // ---- softmax over the 32 selected scores (one per lane) ----
    float v  = iordu(bval);
    float mx = v;
    #pragma unroll
    for (int off = 16; off; off >>= 1)
        mx = fmaxf(mx, __shfl_xor_sync(FULL, mx, off));
    float e = __expf(v - mx);
    float s = e;
    #pragma unroll
    for (int off = 16; off; off >>= 1)
        s += __shfl_xor_sync(FULL, s, off);
    float wgt = e / s;

    // ---- weighted V gather: 32 rows x 64 dims, coalesced 128B halves ----
    const float* vbase = gv + (size_t)(b*H_ + h) * LM_ * DK_;
    float a0 = 0.f, a1 = 0.f;
    #pragma unroll 4
    for (int it = 0; it < TOPK_; it++) {
        float wi = __shfl_sync(FULL, wgt, it);
        int   kk = __shfl_sync(FULL, bidx, it);
        const float* vr = vbase + (size_t)kk * DK_;
        a0 = fmaf(wi, vr[lane],      a0);
        a1 = fmaf(wi, vr[lane + 32], a1);
    }
    float* orow = gx + ((size_t)b * LQ_ + (qt0 + w)) * DM_ + h*DK_;
    orow[lane]      = a0;
    orow[lane + 32] = a1;
}

// ---------------------------------------------------------------------------
extern "C" void kernel_launch(void* const* d_in, const int* in_sizes, int n_in,
                              void* d_out, int out_size)
{
    const float* query = (const float*)d_in[0];
    const float* key   = (const float*)d_in[1];
    const float* value = (const float*)d_in[2];
    const float* Wq    = (const float*)d_in[3];
    const float* bq    = (const float*)d_in[4];
    const float* Wk    = (const float*)d_in[5];
    const float* bk    = (const float*)d_in[6];
    const float* Wv    = (const float*)d_in[7];
    const float* bv    = (const float*)d_in[8];
    const float* Wo    = (const float*)d_in[9];
    const float* bo    = (const float*)d_in[10];
    float* out = (float*)d_out;

    float *pq, *pk, *pv, *px;
    cudaGetSymbolAddress((void**)&pq, g_q);
    cudaGetSymbolAddress((void**)&pk, g_k);
    cudaGetSymbolAddress((void**)&pv, g_v);
    cudaGetSymbolAddress((void**)&px, g_x);

    cudaFuncSetAttribute(attn_topk_kernel,
                         cudaFuncAttributeMaxDynamicSharedMemorySize, SMEM_BYTES);

    // projections into head-major scratch
    gemm512_kernel<<<dim3(B_*LQ_/128, DM_/128), 256>>>(query, Wq, bq, pq, LQ_, 1);
    gemm512_kernel<<<dim3(B_*LM_/128, DM_/128), 256>>>(key,   Wk, bk, pk, LM_, 1);
    gemm512_kernel<<<dim3(B_*LM_/128, DM_/128), 256>>>(value, Wv, bv, pv, LM_, 1);

    // fused scores + topk + softmax + gather
    attn_topk_kernel<<<dim3(LQ_/QT, H_, B_), 256, SMEM_BYTES>>>(pq, pk, pv, px);

    // output projection (plain row-major)
    gemm512_kernel<<<dim3(B_*LQ_/128, DM_/128), 256>>>(px, Wo, bo, out, LQ_, 0);
}

// round 6
// speedup vs baseline: 2.4205x; 1.0101x over previous
#include <cuda_runtime.h>
#include <cstdint>

// Problem constants
constexpr int B_   = 8;
constexpr int H_   = 8;
constexpr int LQ_  = 1024;
constexpr int LM_  = 4096;
constexpr int DM_  = 512;
constexpr int DK_  = 64;
constexpr int TOPK_ = 32;

// Attention kernel tiling
constexpr int QT   = 16;    // queries per block (2 rows per warp)
constexpr int CK   = 128;   // key chunk cached in smem (32 KB)

// Scratch (static device arrays: allocation-free)
__device__ float g_q[B_*H_*LQ_*DK_];   // 16 MB  [B,H,LQ,Dk]
__device__ float g_k[B_*H_*LM_*DK_];   // 64 MB  [B,H,LM,Dk]
__device__ float g_v[B_*H_*LM_*DK_];   // 64 MB  [B,H,LM,Dk]
__device__ float g_x[B_*LQ_*DM_];      // 16 MB  [B,LQ,DM] pre-output-proj

// ---------------- attention smem layout (floats) ---------------------------
constexpr int OFF_QS  = 0;                 // 1024 : Q tile 16x64
constexpr int OFF_KS  = OFF_QS + QT*DK_;   // 8192 : K chunk 128x64, xor-swizzled float4
constexpr int OFF_SCC = OFF_KS + CK*DK_;   // 2048 : score staging 16x128 (ordu uints)
constexpr int SMEM_FLOATS = OFF_SCC + QT*CK;
constexpr int SMEM_BYTES  = SMEM_FLOATS * 4;   // 45056 B -> 4 blocks/SM fits 180 KB

// order-preserving float -> uint, and inverse
__device__ __forceinline__ unsigned ordu(float x) {
    unsigned u = __float_as_uint(x);
    return (u & 0x80000000u) ? ~u : (u | 0x80000000u);
}
__device__ __forceinline__ float iordu(unsigned v) {
    unsigned u = (v & 0x80000000u) ? (v ^ 0x80000000u) : ~v;
    return __uint_as_float(u);
}

// ---------------------------------------------------------------------------
// SGEMM: C = A[M,512] @ W[512,512]^T + bias (torch Linear semantics).
// Double-buffered smem pipeline; per-thread FP arithmetic order IDENTICAL to
// the round-2 passing version (two-level accumulation). UNCHANGED this round.
// grid: (M/128, 4), block: 256 threads, 8x8 per thread.
// ---------------------------------------------------------------------------
__global__ void __launch_bounds__(256, 1)
gemm512_kernel(const float* __restrict__ A, const float* __restrict__ W,
               const float* __restrict__ bias, float* __restrict__ C,
               int L, int head_major)
{
    __shared__ float As[2][8][128];
    __shared__ float Bs[2][8][128];

    const int t  = threadIdx.x;
    const int tx = t & 15;
    const int ty = t >> 4;
    const int m0 = blockIdx.x * 128;
    const int n0 = blockIdx.y * 128;
    const int lr = t >> 1;
    const int lc = (t & 1) << 2;

    const float* Ap = A + (size_t)(m0 + lr) * DM_ + lc;
    const float* Wp = W + (size_t)(n0 + lr) * DM_ + lc;

    float4 av = *(const float4*)(Ap);
    float4 wv = *(const float4*)(Wp);
    As[0][lc+0][lr] = av.x; As[0][lc+1][lr] = av.y; As[0][lc+2][lr] = av.z; As[0][lc+3][lr] = av.w;
    Bs[0][lc+0][lr] = wv.x; Bs[0][lc+1][lr] = wv.y; Bs[0][lc+2][lr] = wv.z; Bs[0][lc+3][lr] = wv.w;
    __syncthreads();

    float acc[8][8];
    #pragma unroll
    for (int i = 0; i < 8; i++)
        #pragma unroll
        for (int j = 0; j < 8; j++) acc[i][j] = 0.f;

    #pragma unroll 1
    for (int k0 = 0; k0 < DM_; k0 += 8) {
        const int  p    = (k0 >> 3) & 1;
        const bool more = (k0 + 8) < DM_;
        if (more) {
            av = *(const float4*)(Ap + k0 + 8);
            wv = *(const float4*)(Wp + k0 + 8);
        }

        float cacc[8][8];
        #pragma unroll
        for (int k = 0; k < 8; k++) {
            float a[8], bb[8];
            #pragma unroll
            for (int i = 0; i < 8; i++) a[i]  = As[p][k][ty*8 + i];
            #pragma unroll
            for (int j = 0; j < 8; j++) bb[j] = Bs[p][k][tx*8 + j];
            if (k == 0) {
                #pragma unroll
                for (int i = 0; i < 8; i++)
                    #pragma unroll
                    for (int j = 0; j < 8; j++)
                        cacc[i][j] = a[i] * bb[j];
            } else {
                #pragma unroll
                for (int i = 0; i < 8; i++)
                    #pragma unroll
                    for (int j = 0; j < 8; j++)
                        cacc[i][j] = fmaf(a[i], bb[j], cacc[i][j]);
            }
        }
        #pragma unroll
        for (int i = 0; i < 8; i++)
            #pragma unroll
            for (int j = 0; j < 8; j++)
                acc[i][j] += cacc[i][j];

        if (more) {
            const int q = p ^ 1;
            As[q][lc+0][lr] = av.x; As[q][lc+1][lr] = av.y; As[q][lc+2][lr] = av.z; As[q][lc+3][lr] = av.w;
            Bs[q][lc+0][lr] = wv.x; Bs[q][lc+1][lr] = wv.y; Bs[q][lc+2][lr] = wv.z; Bs[q][lc+3][lr] = wv.w;
        }
        __syncthreads();
    }

    #pragma unroll
    for (int i = 0; i < 8; i++) {
        int m  = m0 + ty*8 + i;
        int bb_ = m / L;
        int l   = m - bb_ * L;
        #pragma unroll
        for (int j = 0; j < 8; j++) {
            int n = n0 + tx*8 + j;
            float v = acc[i][j] + bias[n];
            if (head_major) {
                int hh = n >> 6, dk = n & 63;
                C[((size_t)(bb_*H_ + hh) * L + l) * DK_ + dk] = v;
            } else {
                C[(size_t)m * DM_ + n] = v;
            }
        }
    }
}

// ---------------------------------------------------------------------------
// Fused scores + EXACT top-32 (running register top-k with threshold
// short-circuit + REDUX) + softmax + V gather.
// One block per (b, h, 16-query tile); 256 threads; warp w owns rows 2w,2w+1.
// Per-(q,k) score expression and per-row selection visit order bit-identical
// to rounds 4/5.
// ---------------------------------------------------------------------------
__global__ void __launch_bounds__(256, 4)
attn_topk_kernel(const float* __restrict__ gq, const float* __restrict__ gk,
                 const float* __restrict__ gv, float* __restrict__ gx)
{
    extern __shared__ float sm[];
    float*    qs  = sm + OFF_QS;
    float*    ks  = sm + OFF_KS;                 // xor-swizzled float4 tile
    unsigned* scC = (unsigned*)(sm + OFF_SCC);   // QT x CK ordu scores

    const int t    = threadIdx.x;
    const int lane = t & 31;
    const int w    = t >> 5;               // warp id; owns query rows 2w, 2w+1
    const int qt0  = blockIdx.x * QT;
    const int h    = blockIdx.y;
    const int b    = blockIdx.z;
    const unsigned FULL = 0xffffffffu;

    // score-phase ownership: key kk in chunk, query group qh (0 or 8)
    const int kk = t & (CK - 1);
    const int qh = (t >> 7) << 3;

    // ---- load Q tile (16x64 fp32) ----
    const float* qbase = gq + ((size_t)(b*H_ + h) * LQ_ + qt0) * DK_;
    if (t < QT*DK_/4) ((float4*)qs)[t] = ((const float4*)qbase)[t];

    const float* kbase = gk + (size_t)(b*H_ + h) * LM_ * DK_;

    // running top-32 state for the two rows owned by this warp
    unsigned bval[2] = {0u, 0u};
    int      bidx[2] = {0, 0};
    unsigned m[2]    = {0u, 0u};

    #pragma unroll 1
    for (int c0 = 0; c0 < LM_; c0 += CK) {
        __syncthreads();  // prev chunk's select done before scC/ks overwrite

        // ---- stage K chunk (CK x 64) with XOR swizzle: conflict-free ----
        #pragma unroll
        for (int i = t; i < CK*16; i += 256) {
            int row = i >> 4, col = i & 15;
            float4 v4 = ((const float4*)(kbase + (size_t)(c0 + row) * DK_))[col];
            ((float4*)ks)[(row << 4) | (col ^ (row & 15))] = v4;
        }
        __syncthreads();

        // ---- scores: all 256 threads; thread owns (key kk, queries qh..qh+7)
        //      per-(q,k) FMA expression identical to rounds 4/5 ----
        {
            float acc[8];
            #pragma unroll
            for (int qi = 0; qi < 8; qi++) acc[qi] = 0.f;
            const float4* ks4 = (const float4*)ks;
            #pragma unroll
            for (int d4 = 0; d4 < DK_/4; d4++) {
                float4 kv = ks4[(kk << 4) | (d4 ^ (kk & 15))];
                #pragma unroll
                for (int qi = 0; qi < 8; qi++) {
                    float4 qv = ((const float4*)(qs + (qh + qi)*DK_))[d4];
                    acc[qi] += kv.x*qv.x + kv.y*qv.y + kv.z*qv.z + kv.w*qv.w;
                }
            }
            #pragma unroll
            for (int qi = 0; qi < 8; qi++)
                scC[(qh + qi)*CK + kk] = ordu(acc[qi] * 0.125f);   // 1/sqrt(64)
        }
        __syncthreads();

        // ---- select: warp w updates running top-32 for rows 2w, 2w+1 ----
        #pragma unroll 1
        for (int rr = 0; rr < 2; rr++) {
            const int rowi = 2*w + rr;
            #pragma unroll 1
            for (int bb = 0; bb < CK/32; bb++) {
                const int i0 = c0 + bb*32;
                unsigned u = scC[rowi*CK + bb*32 + lane];

                if (c0 == 0 && bb == 0) {       // initial fill
                    bval[rr] = u; bidx[rr] = lane;
                    m[rr] = __reduce_min_sync(FULL, bval[rr]);
                    continue;
                }

                unsigned hit = __ballot_sync(FULL, u > m[rr]);
                while (hit) {                    // warp-uniform rare path
                    int s = __ffs(hit) - 1; hit &= hit - 1;
                    unsigned uc = __shfl_sync(FULL, u, s);
                    if (uc > m[rr]) {            // recheck vs updated m
                        int ic = i0 + s;
                        unsigned em = __ballot_sync(FULL, bval[rr] == m[rr]);
                        int el;
                        if (__popc(em) > 1) {
                            // tie on min value: evict LARGER index (jax keeps lower)
                            int cb = ((em >> lane) & 1) ? bidx[rr] : -1;
                            int mx = __reduce_max_sync(FULL, cb);
                            el = __ffs(__ballot_sync(FULL,
                                    (bval[rr] == m[rr]) && (bidx[rr] == mx))) - 1;
                        } else {
                            el = __ffs(em) - 1;
                        }
                        if (lane == el) { bval[rr] = uc; bidx[rr] = ic; }
                        m[rr] = __reduce_min_sync(FULL, bval[rr]);
                    }
                }
            }
        }
    }

    // ---- softmax + weighted V gather for the two rows ----
    const float* vbase = gv + (size_t)(b*H_ + h) * LM_ * DK_;
    #pragma unroll 1
    for (int rr = 0; rr < 2; rr++) {
        float v  = iordu(bval[rr]);
        float mx = v;
        #pragma unroll
        for (int off = 16; off; off >>= 1)
            mx = fmaxf(mx, __shfl_xor_sync(FULL, mx, off));
        float e = __expf(v - mx);
        float s = e;
        #pragma unroll
        for (int off = 16; off; off >>= 1)
            s += __shfl_xor_sync(FULL, s, off);
        float wgt = e / s;

        float a0 = 0.f, a1 = 0.f;
        #pragma unroll 4
        for (int it = 0; it < TOPK_; it++) {
            float wi = __shfl_sync(FULL, wgt, it);
            int   kk2 = __shfl_sync(FULL, bidx[rr], it);
            const float* vr = vbase + (size_t)kk2 * DK_;
            a0 = fmaf(wi, vr[lane],      a0);
            a1 = fmaf(wi, vr[lane + 32], a1);
        }
        float* orow = gx + ((size_t)b * LQ_ + (qt0 + 2*w + rr)) * DM_ + h*DK_;
        orow[lane]      = a0;
        orow[lane + 32] = a1;
    }
}

// ---------------------------------------------------------------------------
extern "C" void kernel_launch(void* const* d_in, const int* in_sizes, int n_in,
                              void* d_out, int out_size)
{
    const float* query = (const float*)d_in[0];
    const float* key   = (const float*)d_in[1];
    const float* value = (const float*)d_in[2];
    const float* Wq    = (const float*)d_in[3];
    const float* bq    = (const float*)d_in[4];
    const float* Wk    = (const float*)d_in[5];
    const float* bk    = (const float*)d_in[6];
    const float* Wv    = (const float*)d_in[7];
    const float* bv    = (const float*)d_in[8];
    const float* Wo    = (const float*)d_in[9];
    const float* bo    = (const float*)d_in[10];
    float* out = (float*)d_out;

    float *pq, *pk, *pv, *px;
    cudaGetSymbolAddress((void**)&pq, g_q);
    cudaGetSymbolAddress((void**)&pk, g_k);
    cudaGetSymbolAddress((void**)&pv, g_v);
    cudaGetSymbolAddress((void**)&px, g_x);

    cudaFuncSetAttribute(attn_topk_kernel,
                         cudaFuncAttributeMaxDynamicSharedMemorySize, SMEM_BYTES);

    // projections into head-major scratch
    gemm512_kernel<<<dim3(B_*LQ_/128, DM_/128), 256>>>(query, Wq, bq, pq, LQ_, 1);
    gemm512_kernel<<<dim3(B_*LM_/128, DM_/128), 256>>>(key,   Wk, bk, pk, LM_, 1);
    gemm512_kernel<<<dim3(B_*LM_/128, DM_/128), 256>>>(value, Wv, bv, pv, LM_, 1);

    // fused scores + topk + softmax + gather
    attn_topk_kernel<<<dim3(LQ_/QT, H_, B_), 256, SMEM_BYTES>>>(pq, pk, pv, px);

    // output projection (plain row-major)
    gemm512_kernel<<<dim3(B_*LQ_/128, DM_/128), 256>>>(px, Wo, bo, out, LQ_, 0);
}

// round 7
// speedup vs baseline: 2.6555x; 1.0971x over previous
#include <cuda_runtime.h>
#include <cstdint>

// Problem constants
constexpr int B_   = 8;
constexpr int H_   = 8;
constexpr int LQ_  = 1024;
constexpr int LM_  = 4096;
constexpr int DM_  = 512;
constexpr int DK_  = 64;
constexpr int TOPK_ = 32;

// Attention kernel tiling
constexpr int QT   = 32;    // queries per block (4 rows per warp)
constexpr int CK   = 128;   // key chunk cached in smem (32 KB)

// Scratch (static device arrays: allocation-free)
__device__ float g_q[B_*H_*LQ_*DK_];   // 16 MB  [B,H,LQ,Dk]
__device__ float g_k[B_*H_*LM_*DK_];   // 64 MB  [B,H,LM,Dk]
__device__ float g_v[B_*H_*LM_*DK_];   // 64 MB  [B,H,LM,Dk]
__device__ float g_x[B_*LQ_*DM_];      // 16 MB  [B,LQ,DM] pre-output-proj

// ---------------- attention smem layout (floats) ---------------------------
constexpr int OFF_QS  = 0;                 // 2048 : Q tile 32x64
constexpr int OFF_KS  = OFF_QS + QT*DK_;   // 8192 : K chunk 128x64, xor-swizzled float4
constexpr int OFF_SCC = OFF_KS + CK*DK_;   // 4096 : score staging 32x128 (ordu uints)
constexpr int SMEM_FLOATS = OFF_SCC + QT*CK;
constexpr int SMEM_BYTES  = SMEM_FLOATS * 4;   // 57344 B -> 3 blocks/SM

// order-preserving float -> uint, and inverse
__device__ __forceinline__ unsigned ordu(float x) {
    unsigned u = __float_as_uint(x);
    return (u & 0x80000000u) ? ~u : (u | 0x80000000u);
}
__device__ __forceinline__ float iordu(unsigned v) {
    unsigned u = (v & 0x80000000u) ? (v ^ 0x80000000u) : ~v;
    return __uint_as_float(u);
}

// ---------------------------------------------------------------------------
// Shared SGEMM body: C = A[M,512] @ W[512,512]^T + bias (torch Linear).
// Double-buffered smem pipeline; per-thread FP arithmetic order IDENTICAL to
// the round-2..6 passing versions (two-level accumulation).
// 256 threads, 8x8 per thread, 128x128 tile at (m0, n0).
// ---------------------------------------------------------------------------
__device__ __forceinline__ void gemm_body(
    const float* __restrict__ A, const float* __restrict__ W,
    const float* __restrict__ bias, float* __restrict__ C,
    int L, int head_major, int m0, int n0)
{
    __shared__ float As[2][8][128];
    __shared__ float Bs[2][8][128];

    const int t  = threadIdx.x;
    const int tx = t & 15;
    const int ty = t >> 4;
    const int lr = t >> 1;
    const int lc = (t & 1) << 2;

    const float* Ap = A + (size_t)(m0 + lr) * DM_ + lc;
    const float* Wp = W + (size_t)(n0 + lr) * DM_ + lc;

    float4 av = *(const float4*)(Ap);
    float4 wv = *(const float4*)(Wp);
    As[0][lc+0][lr] = av.x; As[0][lc+1][lr] = av.y; As[0][lc+2][lr] = av.z; As[0][lc+3][lr] = av.w;
    Bs[0][lc+0][lr] = wv.x; Bs[0][lc+1][lr] = wv.y; Bs[0][lc+2][lr] = wv.z; Bs[0][lc+3][lr] = wv.w;
    __syncthreads();

    float acc[8][8];
    #pragma unroll
    for (int i = 0; i < 8; i++)
        #pragma unroll
        for (int j = 0; j < 8; j++) acc[i][j] = 0.f;

    #pragma unroll 1
    for (int k0 = 0; k0 < DM_; k0 += 8) {
        const int  p    = (k0 >> 3) & 1;
        const bool more = (k0 + 8) < DM_;
        if (more) {
            av = *(const float4*)(Ap + k0 + 8);
            wv = *(const float4*)(Wp + k0 + 8);
        }

        float cacc[8][8];
        #pragma unroll
        for (int k = 0; k < 8; k++) {
            float a[8], bb[8];
            #pragma unroll
            for (int i = 0; i < 8; i++) a[i]  = As[p][k][ty*8 + i];
            #pragma unroll
            for (int j = 0; j < 8; j++) bb[j] = Bs[p][k][tx*8 + j];
            if (k == 0) {
                #pragma unroll
                for (int i = 0; i < 8; i++)
                    #pragma unroll
                    for (int j = 0; j < 8; j++)
                        cacc[i][j] = a[i] * bb[j];
            } else {
                #pragma unroll
                for (int i = 0; i < 8; i++)
                    #pragma unroll
                    for (int j = 0; j < 8; j++)
                        cacc[i][j] = fmaf(a[i], bb[j], cacc[i][j]);
            }
        }
        #pragma unroll
        for (int i = 0; i < 8; i++)
            #pragma unroll
            for (int j = 0; j < 8; j++)
                acc[i][j] += cacc[i][j];

        if (more) {
            const int q = p ^ 1;
            As[q][lc+0][lr] = av.x; As[q][lc+1][lr] = av.y; As[q][lc+2][lr] = av.z; As[q][lc+3][lr] = av.w;
            Bs[q][lc+0][lr] = wv.x; Bs[q][lc+1][lr] = wv.y; Bs[q][lc+2][lr] = wv.z; Bs[q][lc+3][lr] = wv.w;
        }
        __syncthreads();
    }

    #pragma unroll
    for (int i = 0; i < 8; i++) {
        int m  = m0 + ty*8 + i;
        int bb_ = m / L;
        int l   = m - bb_ * L;
        #pragma unroll
        for (int j = 0; j < 8; j++) {
            int n = n0 + tx*8 + j;
            float v = acc[i][j] + bias[n];
            if (head_major) {
                int hh = n >> 6, dk = n & 63;
                C[((size_t)(bb_*H_ + hh) * L + l) * DK_ + dk] = v;
            } else {
                C[(size_t)m * DM_ + n] = v;
            }
        }
    }
}

// Merged Q/K/V projection: grid (64 + 256 + 256, 4).
__global__ void __launch_bounds__(256, 1)
qkv_gemm_kernel(const float* __restrict__ q_in, const float* __restrict__ k_in,
                const float* __restrict__ v_in,
                const float* __restrict__ Wq, const float* __restrict__ bq,
                const float* __restrict__ Wk, const float* __restrict__ bk,
                const float* __restrict__ Wv, const float* __restrict__ bv,
                float* __restrict__ pq, float* __restrict__ pk, float* __restrict__ pv)
{
    const int bx = blockIdx.x;
    const float *A, *W, *bias; float* C; int L, mblk;
    if (bx < 64)        { A = q_in; W = Wq; bias = bq; C = pq; L = LQ_; mblk = bx; }
    else if (bx < 320)  { A = k_in; W = Wk; bias = bk; C = pk; L = LM_; mblk = bx - 64; }
    else                { A = v_in; W = Wv; bias = bv; C = pv; L = LM_; mblk = bx - 320; }
    gemm_body(A, W, bias, C, L, 1, mblk * 128, blockIdx.y * 128);
}

// Output projection: plain row-major.
__global__ void __launch_bounds__(256, 1)
out_gemm_kernel(const float* __restrict__ A, const float* __restrict__ W,
                const float* __restrict__ bias, float* __restrict__ C)
{
    gemm_body(A, W, bias, C, LQ_, 0, blockIdx.x * 128, blockIdx.y * 128);
}

// ---------------------------------------------------------------------------
// Fused scores + EXACT top-32 (running register top-k, uint4 skip fast path)
// + softmax + V gather.
// One block per (b, h, 32-query tile); 256 threads; warp w owns rows 4w..4w+3.
// Score phase: thread owns 2 keys x 8 queries; per-(q,k) FMA expression is
// the same source statement as rounds 4-6; per-row selection visit order is
// ascending key index (bit-identical selection).
// ---------------------------------------------------------------------------
__global__ void __launch_bounds__(256, 3)
attn_topk_kernel(const float* __restrict__ gq, const float* __restrict__ gk,
                 const float* __restrict__ gv, float* __restrict__ gx)
{
    extern __shared__ float sm[];
    float*    qs  = sm + OFF_QS;
    float*    ks  = sm + OFF_KS;                 // xor-swizzled float4 tile
    unsigned* scC = (unsigned*)(sm + OFF_SCC);   // QT x CK ordu scores

    const int t    = threadIdx.x;
    const int lane = t & 31;
    const int w    = t >> 5;               // warp id; owns rows 4w..4w+3
    const int qt0  = blockIdx.x * QT;
    const int h    = blockIdx.y;
    const int b    = blockIdx.z;
    const unsigned FULL = 0xffffffffu;

    // score-phase ownership: keys {kk, kk+64}, queries qh..qh+7
    const int kk = t & 63;
    const int qh = (t >> 6) << 3;

    // ---- load Q tile (32x64 fp32) ----
    const float* qbase = gq + ((size_t)(b*H_ + h) * LQ_ + qt0) * DK_;
    #pragma unroll
    for (int i = t; i < QT*DK_/4; i += 256)
        ((float4*)qs)[i] = ((const float4*)qbase)[i];

    const float* kbase = gk + (size_t)(b*H_ + h) * LM_ * DK_;

    // running top-32 state for the four rows owned by this warp
    unsigned bval[4] = {0u, 0u, 0u, 0u};
    int      bidx[4] = {0, 0, 0, 0};
    unsigned m[4]    = {0u, 0u, 0u, 0u};

    #pragma unroll 1
    for (int c0 = 0; c0 < LM_; c0 += CK) {
        __syncthreads();  // prev chunk's select done before scC/ks overwrite

        // ---- stage K chunk (CK x 64) with XOR swizzle: conflict-free ----
        #pragma unroll
        for (int i = t; i < CK*16; i += 256) {
            int row = i >> 4, col = i & 15;
            float4 v4 = ((const float4*)(kbase + (size_t)(c0 + row) * DK_))[col];
            ((float4*)ks)[(row << 4) | (col ^ (row & 15))] = v4;
        }
        __syncthreads();

        // ---- scores: thread owns keys kk, kk+64 and queries qh..qh+7;
        //      per-(q,k) FMA statement identical to rounds 4-6 ----
        {
            float acc0[8], acc1[8];
            #pragma unroll
            for (int qi = 0; qi < 8; qi++) { acc0[qi] = 0.f; acc1[qi] = 0.f; }
            const float4* ks4 = (const float4*)ks;
            const int kk2 = kk + 64;
            #pragma unroll
            for (int d4 = 0; d4 < DK_/4; d4++) {
                float4 kv0 = ks4[(kk  << 4) | (d4 ^ (kk  & 15))];
                float4 kv1 = ks4[(kk2 << 4) | (d4 ^ (kk2 & 15))];
                #pragma unroll
                for (int qi = 0; qi < 8; qi++) {
                    float4 qv = ((const float4*)(qs + (qh + qi)*DK_))[d4];
                    acc0[qi] += kv0.x*qv.x + kv0.y*qv.y + kv0.z*qv.z + kv0.w*qv.w;
                    acc1[qi] += kv1.x*qv.x + kv1.y*qv.y + kv1.z*qv.z + kv1.w*qv.w;
                }
            }
            #pragma unroll
            for (int qi = 0; qi < 8; qi++) {
                scC[(qh + qi)*CK + kk ] = ordu(acc0[qi] * 0.125f);  // 1/sqrt(64)
                scC[(qh + qi)*CK + kk2] = ordu(acc1[qi] * 0.125f);
            }
        }
        __syncthreads();

        // ---- select: warp w updates running top-32 for rows 4w..4w+3 ----
        #pragma unroll 1
        for (int rr = 0; rr < 4; rr++) {
            const int rowi = 4*w + rr;
            const unsigned* srow = scC + rowi*CK;

            bool slow;
            if (c0 == 0) {
                slow = true;   // includes initial fill
            } else {
                // fast path: one uint4 per lane covers the 128-key chunk.
                // Skipping when nothing exceeds m is exactly equivalent to
                // sequential processing (m is monotone non-decreasing).
                uint4 uu = ((const uint4*)srow)[lane];
                bool any = (uu.x > m[rr]) | (uu.y > m[rr]) |
                           (uu.z > m[rr]) | (uu.w > m[rr]);
                slow = (__ballot_sync(FULL, any) != 0u);
            }

            if (slow) {
                #pragma unroll 1
                for (int bb = 0; bb < CK/32; bb++) {
                    const int i0 = c0 + bb*32;
                    unsigned u = srow[bb*32 + lane];

                    if (c0 == 0 && bb == 0) {       // initial fill
                        bval[rr] = u; bidx[rr] = lane;
                        m[rr] = __reduce_min_sync(FULL, bval[rr]);
                        continue;
                    }

                    unsigned hit = __ballot_sync(FULL, u > m[rr]);
                    while (hit) {                    // warp-uniform rare path
                        int s = __ffs(hit) - 1; hit &= hit - 1;
                        unsigned uc = __shfl_sync(FULL, u, s);
                        if (uc > m[rr]) {            // recheck vs updated m
                            int ic = i0 + s;
                            unsigned em = __ballot_sync(FULL, bval[rr] == m[rr]);
                            int el;
                            if (__popc(em) > 1) {
                                // tie on min: evict LARGER index (jax keeps lower)
                                int cb = ((em >> lane) & 1) ? bidx[rr] : -1;
                                int mx = __reduce_max_sync(FULL, cb);
                                el = __ffs(__ballot_sync(FULL,
                                        (bval[rr] == m[rr]) && (bidx[rr] == mx))) - 1;
                            } else {
                                el = __ffs(em) - 1;
                            }
                            if (lane == el) { bval[rr] = uc; bidx[rr] = ic; }
                            m[rr] = __reduce_min_sync(FULL, bval[rr]);
                        }
                    }
                }
            }
        }
    }

    // ---- softmax + weighted V gather for the four rows ----
    const float* vbase = gv + (size_t)(b*H_ + h) * LM_ * DK_;
    #pragma unroll 1
    for (int rr = 0; rr < 4; rr++) {
        float v  = iordu(bval[rr]);
        float mx = v;
        #pragma unroll
        for (int off = 16; off; off >>= 1)
            mx = fmaxf(mx, __shfl_xor_sync(FULL, mx, off));
        float e = __expf(v - mx);
        float s = e;
        #pragma unroll
        for (int off = 16; off; off >>= 1)
            s += __shfl_xor_sync(FULL, s, off);
        float wgt = e / s;

        float a0 = 0.f, a1 = 0.f;
        #pragma unroll 4
        for (int it = 0; it < TOPK_; it++) {
            float wi = __shfl_sync(FULL, wgt, it);
            int   ki = __shfl_sync(FULL, bidx[rr], it);
            const float* vr = vbase + (size_t)ki * DK_;
            a0 = fmaf(wi, vr[lane],      a0);
            a1 = fmaf(wi, vr[lane + 32], a1);
        }
        float* orow = gx + ((size_t)b * LQ_ + (qt0 + 4*w + rr)) * DM_ + h*DK_;
        orow[lane]      = a0;
        orow[lane + 32] = a1;
    }
}

// ---------------------------------------------------------------------------
extern "C" void kernel_launch(void* const* d_in, const int* in_sizes, int n_in,
                              void* d_out, int out_size)
{
    const float* query = (const float*)d_in[0];
    const float* key   = (const float*)d_in[1];
    const float* value = (const float*)d_in[2];
    const float* Wq    = (const float*)d_in[3];
    const float* bq    = (const float*)d_in[4];
    const float* Wk    = (const float*)d_in[5];
    const float* bk    = (const float*)d_in[6];
    const float* Wv    = (const float*)d_in[7];
    const float* bv    = (const float*)d_in[8];
    const float* Wo    = (const float*)d_in[9];
    const float* bo    = (const float*)d_in[10];
    float* out = (float*)d_out;

    float *pq, *pk, *pv, *px;
    cudaGetSymbolAddress((void**)&pq, g_q);
    cudaGetSymbolAddress((void**)&pk, g_k);
    cudaGetSymbolAddress((void**)&pv, g_v);
    cudaGetSymbolAddress((void**)&px, g_x);

    cudaFuncSetAttribute(attn_topk_kernel,
                         cudaFuncAttributeMaxDynamicSharedMemorySize, SMEM_BYTES);

    // merged Q/K/V projections into head-major scratch
    qkv_gemm_kernel<<<dim3(576, DM_/128), 256>>>(query, key, value,
                                                 Wq, bq, Wk, bk, Wv, bv,
                                                 pq, pk, pv);

    // fused scores + topk + softmax + gather
    attn_topk_kernel<<<dim3(LQ_/QT, H_, B_), 256, SMEM_BYTES>>>(pq, pk, pv, px);

    // output projection (plain row-major)
    out_gemm_kernel<<<dim3(B_*LQ_/128, DM_/128), 256>>>(px, Wo, bo, out);
}

// round 8
// speedup vs baseline: 2.6825x; 1.0102x over previous
#include <cuda_runtime.h>
#include <cstdint>

// Problem constants
constexpr int B_   = 8;
constexpr int H_   = 8;
constexpr int LQ_  = 1024;
constexpr int LM_  = 4096;
constexpr int DM_  = 512;
constexpr int DK_  = 64;
constexpr int TOPK_ = 32;

// Attention kernel tiling
constexpr int QT   = 32;    // queries per block (4 rows per warp)
constexpr int CK   = 128;   // key chunk cached in smem (32 KB)

// Scratch (static device arrays: allocation-free)
__device__ float g_q[B_*H_*LQ_*DK_];   // 16 MB  [B,H,LQ,Dk]
__device__ float g_k[B_*H_*LM_*DK_];   // 64 MB  [B,H,LM,Dk]
__device__ float g_v[B_*H_*LM_*DK_];   // 64 MB  [B,H,LM,Dk]
__device__ float g_x[B_*LQ_*DM_];      // 16 MB  [B,LQ,DM] pre-output-proj

// ---------------- attention smem layout (floats) ---------------------------
constexpr int OFF_QS  = 0;                 // 2048 : Q tile 32x64
constexpr int OFF_KS  = OFF_QS + QT*DK_;   // 8192 : K chunk 128x64, xor-swizzled float4
constexpr int OFF_SCC = OFF_KS + CK*DK_;   // 4096 : score staging 32x128 (ordu uints)
constexpr int SMEM_FLOATS = OFF_SCC + QT*CK;
constexpr int SMEM_BYTES  = SMEM_FLOATS * 4;   // 57344 B -> 3 blocks/SM

// order-preserving float -> uint, and inverse
__device__ __forceinline__ unsigned ordu(float x) {
    unsigned u = __float_as_uint(x);
    return (u & 0x80000000u) ? ~u : (u | 0x80000000u);
}
__device__ __forceinline__ float iordu(unsigned v) {
    unsigned u = (v & 0x80000000u) ? (v ^ 0x80000000u) : ~v;
    return __uint_as_float(u);
}

// ---------------- packed f32x2 primitives (lanewise IEEE fp32) -------------
typedef unsigned long long ull;

__device__ __forceinline__ ull pack2(float lo, float hi) {
    ull d; asm("mov.b64 %0, {%1, %2};" : "=l"(d) : "f"(lo), "f"(hi)); return d;
}
__device__ __forceinline__ void unpack2(ull v, float& lo, float& hi) {
    asm("mov.b64 {%0, %1}, %2;" : "=f"(lo), "=f"(hi) : "l"(v));
}
__device__ __forceinline__ ull fma2(ull a, ull b, ull c) {
    ull d; asm("fma.rn.f32x2 %0, %1, %2, %3;" : "=l"(d) : "l"(a), "l"(b), "l"(c)); return d;
}
__device__ __forceinline__ ull mul2(ull a, ull b) {
    ull d; asm("mul.rn.f32x2 %0, %1, %2;" : "=l"(d) : "l"(a), "l"(b)); return d;
}
__device__ __forceinline__ ull add2(ull a, ull b) {
    ull d; asm("add.rn.f32x2 %0, %1, %2;" : "=l"(d) : "l"(a), "l"(b)); return d;
}

// B smem row layout: per-tx pad to 10 floats -> 16 distinct banks for the
// 16 tx groups (10*tx mod 32 all distinct), 8B-aligned pairs for LDS.64.
constexpr int BROW = 160;   // 16 tx-groups * 10 floats
__device__ __forceinline__ int bswz(int n) { return (n >> 3) * 10 + (n & 7); }

// ---------------------------------------------------------------------------
// Shared SGEMM body: C = A[M,512] @ W[512,512]^T + bias (torch Linear).
// f32x2 packed FMA inner loop. Per-element arithmetic (values and order) is
// IDENTICAL to the scalar two-level version of rounds 2-7:
//   cacc[i][j] = a0*b0 then fma chain over k; acc[i][j] += cacc[i][j].
// A is stored duplicated in smem -> (a,a) multiplicand is one broadcast load.
// 256 threads, 8x8 per thread, 128x128 tile at (m0, n0).
// ---------------------------------------------------------------------------
__device__ __forceinline__ void gemm_body(
    const float* __restrict__ A, const float* __restrict__ W,
    const float* __restrict__ bias, float* __restrict__ C,
    int L, int head_major, int m0, int n0)
{
    __shared__ __align__(16) float AsD[2][8][256];   // duplicated A: 16 KB
    __shared__ __align__(16) float Bs [2][8][BROW];  // padded B: 10 KB

    const int t  = threadIdx.x;
    const int tx = t & 15;
    const int ty = t >> 4;
    const int lr = t >> 1;
    const int lc = (t & 1) << 2;

    const float* Ap = A + (size_t)(m0 + lr) * DM_ + lc;
    const float* Wp = W + (size_t)(n0 + lr) * DM_ + lc;
    const int bofs = bswz(lr);

    // prologue: stage k-tile 0 into buffer 0
    {
        float4 av = *(const float4*)(Ap);
        float4 wv = *(const float4*)(Wp);
        ((ull*)AsD[0][lc+0])[lr] = pack2(av.x, av.x);
        ((ull*)AsD[0][lc+1])[lr] = pack2(av.y, av.y);
        ((ull*)AsD[0][lc+2])[lr] = pack2(av.z, av.z);
        ((ull*)AsD[0][lc+3])[lr] = pack2(av.w, av.w);
        Bs[0][lc+0][bofs] = wv.x;
        Bs[0][lc+1][bofs] = wv.y;
        Bs[0][lc+2][bofs] = wv.z;
        Bs[0][lc+3][bofs] = wv.w;
    }
    __syncthreads();

    ull acc2[8][4];
    #pragma unroll
    for (int i = 0; i < 8; i++)
        #pragma unroll
        for (int j = 0; j < 4; j++) acc2[i][j] = pack2(0.f, 0.f);

    #pragma unroll 1
    for (int k0 = 0; k0 < DM_; k0 += 8) {
        const int  p    = (k0 >> 3) & 1;
        const bool more = (k0 + 8) < DM_;
        float4 av, wv;
        if (more) {
            av = *(const float4*)(Ap + k0 + 8);
            wv = *(const float4*)(Wp + k0 + 8);
        }

        ull cacc2[8][4];
        #pragma unroll
        for (int k = 0; k < 8; k++) {
            // a (duplicated) : 8 ull = 4x LDS.128 broadcast
            ull a2[8];
            {
                const ulonglong2* ar = (const ulonglong2*)&AsD[p][k][0];
                #pragma unroll
                for (int ii = 0; ii < 4; ii++) {
                    ulonglong2 v = ar[ty*4 + ii];
                    a2[2*ii]   = v.x;
                    a2[2*ii+1] = v.y;
                }
            }
            // b pairs: 4x LDS.64, conflict-free via 10-float padding
            ull b2[4];
            {
                const ull* br = (const ull*)&Bs[p][k][tx*10];
                #pragma unroll
                for (int j = 0; j < 4; j++) b2[j] = br[j];
            }
            if (k == 0) {
                #pragma unroll
                for (int i = 0; i < 8; i++)
                    #pragma unroll
                    for (int j = 0; j < 4; j++)
                        cacc2[i][j] = mul2(a2[i], b2[j]);
            } else {
                #pragma unroll
                for (int i = 0; i < 8; i++)
                    #pragma unroll
                    for (int j = 0; j < 4; j++)
                        cacc2[i][j] = fma2(a2[i], b2[j], cacc2[i][j]);
            }
        }
        #pragma unroll
        for (int i = 0; i < 8; i++)
            #pragma unroll
            for (int j = 0; j < 4; j++)
                acc2[i][j] = add2(acc2[i][j], cacc2[i][j]);

        if (more) {
            const int q = p ^ 1;
            ((ull*)AsD[q][lc+0])[lr] = pack2(av.x, av.x);
            ((ull*)AsD[q][lc+1])[lr] = pack2(av.y, av.y);
            ((ull*)AsD[q][lc+2])[lr] = pack2(av.z, av.z);
            ((ull*)AsD[q][lc+3])[lr] = pack2(av.w, av.w);
            Bs[q][lc+0][bofs] = wv.x;
            Bs[q][lc+1][bofs] = wv.y;
            Bs[q][lc+2][bofs] = wv.z;
            Bs[q][lc+3][bofs] = wv.w;
        }
        __syncthreads();
    }

    #pragma unroll
    for (int i = 0; i < 8; i++) {
        int m  = m0 + ty*8 + i;
        int bb_ = m / L;
        int l   = m - bb_ * L;
        #pragma unroll
        for (int j = 0; j < 4; j++) {
            float lo, hi;
            unpack2(acc2[i][j], lo, hi);
            int n0j = n0 + tx*8 + 2*j;
            float v0 = lo + bias[n0j];
            float v1 = hi + bias[n0j + 1];
            if (head_major) {
                int hh0 = n0j >> 6, dk0 = n0j & 63;
                int hh1 = (n0j+1) >> 6, dk1 = (n0j+1) & 63;
                C[((size_t)(bb_*H_ + hh0) * L + l) * DK_ + dk0] = v0;
                C[((size_t)(bb_*H_ + hh1) * L + l) * DK_ + dk1] = v1;
            } else {
                C[(size_t)m * DM_ + n0j]     = v0;
                C[(size_t)m * DM_ + n0j + 1] = v1;
            }
        }
    }
}

// Merged Q/K/V projection: grid (64 + 256 + 256, 4).
__global__ void __launch_bounds__(256, 1)
qkv_gemm_kernel(const float* __restrict__ q_in, const float* __restrict__ k_in,
                const float* __restrict__ v_in,
                const float* __restrict__ Wq, const float* __restrict__ bq,
                const float* __restrict__ Wk, const float* __restrict__ bk,
                const float* __restrict__ Wv, const float* __restrict__ bv,
                float* __restrict__ pq, float* __restrict__ pk, float* __restrict__ pv)
{
    const int bx = blockIdx.x;
    const float *A, *W, *bias; float* C; int L, mblk;
    if (bx < 64)        { A = q_in; W = Wq; bias = bq; C = pq; L = LQ_; mblk = bx; }
    else if (bx < 320)  { A = k_in; W = Wk; bias = bk; C = pk; L = LM_; mblk = bx - 64; }
    else                { A = v_in; W = Wv; bias = bv; C = pv; L = LM_; mblk = bx - 320; }
    gemm_body(A, W, bias, C, L, 1, mblk * 128, blockIdx.y * 128);
}

// Output projection: plain row-major.
__global__ void __launch_bounds__(256, 1)
out_gemm_kernel(const float* __restrict__ A, const float* __restrict__ W,
                const float* __restrict__ bias, float* __restrict__ C)
{
    gemm_body(A, W, bias, C, LQ_, 0, blockIdx.x * 128, blockIdx.y * 128);
}

// ---------------------------------------------------------------------------
// Fused scores + EXACT top-32 (running register top-k, uint4 skip fast path)
// + softmax + V gather. UNCHANGED from round 7 (bit-identical selection).
// One block per (b, h, 32-query tile); 256 threads; warp w owns rows 4w..4w+3.
// ---------------------------------------------------------------------------
__global__ void __launch_bounds__(256, 3)
attn_topk_kernel(const float* __restrict__ gq, const float* __restrict__ gk,
                 const float* __restrict__ gv, float* __restrict__ gx)
{
    extern __shared__ float sm[];
    float*    qs  = sm + OFF_QS;
    float*    ks  = sm + OFF_KS;                 // xor-swizzled float4 tile
    unsigned* scC = (unsigned*)(sm + OFF_SCC);   // QT x CK ordu scores

    const int t    = threadIdx.x;
    const int lane = t & 31;
    const int w    = t >> 5;               // warp id; owns rows 4w..4w+3
    const int qt0  = blockIdx.x * QT;
    const int h    = blockIdx.y;
    const int b    = blockIdx.z;
    const unsigned FULL = 0xffffffffu;

    // score-phase ownership: keys {kk, kk+64}, queries qh..qh+7
    const int kk = t & 63;
    const int qh = (t >> 6) << 3;

    // ---- load Q tile (32x64 fp32) ----
    const float* qbase = gq + ((size_t)(b*H_ + h) * LQ_ + qt0) * DK_;
    #pragma unroll
    for (int i = t; i < QT*DK_/4; i += 256)
        ((float4*)qs)[i] = ((const float4*)qbase)[i];

    const float* kbase = gk + (size_t)(b*H_ + h) * LM_ * DK_;

    // running top-32 state for the four rows owned by this warp
    unsigned bval[4] = {0u, 0u, 0u, 0u};
    int      bidx[4] = {0, 0, 0, 0};
    unsigned m[4]    = {0u, 0u, 0u, 0u};

    #pragma unroll 1
    for (int c0 = 0; c0 < LM_; c0 += CK) {
        __syncthreads();  // prev chunk's select done before scC/ks overwrite

        // ---- stage K chunk (CK x 64) with XOR swizzle: conflict-free ----
        #pragma unroll
        for (int i = t; i < CK*16; i += 256) {
            int row = i >> 4, col = i & 15;
            float4 v4 = ((const float4*)(kbase + (size_t)(c0 + row) * DK_))[col];
            ((float4*)ks)[(row << 4) | (col ^ (row & 15))] = v4;
        }
        __syncthreads();

        // ---- scores: thread owns keys kk, kk+64 and queries qh..qh+7;
        //      per-(q,k) FMA statement identical to rounds 4-7 ----
        {
            float acc0[8], acc1[8];
            #pragma unroll
            for (int qi = 0; qi < 8; qi++) { acc0[qi] = 0.f; acc1[qi] = 0.f; }
            const float4* ks4 = (const float4*)ks;
            const int kk2 = kk + 64;
            #pragma unroll
            for (int d4 = 0; d4 < DK_/4; d4++) {
                float4 kv0 = ks4[(kk  << 4) | (d4 ^ (kk  & 15))];
                float4 kv1 = ks4[(kk2 << 4) | (d4 ^ (kk2 & 15))];
                #pragma unroll
                for (int qi = 0; qi < 8; qi++) {
                    float4 qv = ((const float4*)(qs + (qh + qi)*DK_))[d4];
                    acc0[qi] += kv0.x*qv.x + kv0.y*qv.y + kv0.z*qv.z + kv0.w*qv.w;
                    acc1[qi] += kv1.x*qv.x + kv1.y*qv.y + kv1.z*qv.z + kv1.w*qv.w;
                }
            }
            #pragma unroll
            for (int qi = 0; qi < 8; qi++) {
                scC[(qh + qi)*CK + kk ] = ordu(acc0[qi] * 0.125f);  // 1/sqrt(64)
                scC[(qh + qi)*CK + kk2] = ordu(acc1[qi] * 0.125f);
            }
        }
        __syncthreads();

        // ---- select: warp w updates running top-32 for rows 4w..4w+3 ----
        #pragma unroll 1
        for (int rr = 0; rr < 4; rr++) {
            const int rowi = 4*w + rr;
            const unsigned* srow = scC + rowi*CK;

            bool slow;
            if (c0 == 0) {
                slow = true;   // includes initial fill
            } else {
                // fast path: one uint4 per lane covers the 128-key chunk.
                // Skipping when nothing exceeds m is exactly equivalent to
                // sequential processing (m is monotone non-decreasing).
                uint4 uu = ((const uint4*)srow)[lane];
                bool any = (uu.x > m[rr]) | (uu.y > m[rr]) |
                           (uu.z > m[rr]) | (uu.w > m[rr]);
                slow = (__ballot_sync(FULL, any) != 0u);
            }

            if (slow) {
                #pragma unroll 1
                for (int bb = 0; bb < CK/32; bb++) {
                    const int i0 = c0 + bb*32;
                    unsigned u = srow[bb*32 + lane];

                    if (c0 == 0 && bb == 0) {       // initial fill
                        bval[rr] = u; bidx[rr] = lane;
                        m[rr] = __reduce_min_sync(FULL, bval[rr]);
                        continue;
                    }

                    unsigned hit = __ballot_sync(FULL, u > m[rr]);
                    while (hit) {                    // warp-uniform rare path
                        int s = __ffs(hit) - 1; hit &= hit - 1;
                        unsigned uc = __shfl_sync(FULL, u, s);
                        if (uc > m[rr]) {            // recheck vs updated m
                            int ic = i0 + s;
                            unsigned em = __ballot_sync(FULL, bval[rr] == m[rr]);
                            int el;
                            if (__popc(em) > 1) {
                                // tie on min: evict LARGER index (jax keeps lower)
                                int cb = ((em >> lane) & 1) ? bidx[rr] : -1;
                                int mx = __reduce_max_sync(FULL, cb);
                                el = __ffs(__ballot_sync(FULL,
                                        (bval[rr] == m[rr]) && (bidx[rr] == mx))) - 1;
                            } else {
                                el = __ffs(em) - 1;
                            }
                            if (lane == el) { bval[rr] = uc; bidx[rr] = ic; }
                            m[rr] = __reduce_min_sync(FULL, bval[rr]);
                        }
                    }
                }
            }
        }
    }

    // ---- softmax + weighted V gather for the four rows ----
    const float* vbase = gv + (size_t)(b*H_ + h) * LM_ * DK_;
    #pragma unroll 1
    for (int rr = 0; rr < 4; rr++) {
        float v  = iordu(bval[rr]);
        float mx = v;
        #pragma unroll
        for (int off = 16; off; off >>= 1)
            mx = fmaxf(mx, __shfl_xor_sync(FULL, mx, off));
        float e = __expf(v - mx);
        float s = e;
        #pragma unroll
        for (int off = 16; off; off >>= 1)
            s += __shfl_xor_sync(FULL, s, off);
        float wgt = e / s;

        float a0 = 0.f, a1 = 0.f;
        #pragma unroll 4
        for (int it = 0; it < TOPK_; it++) {
            float wi = __shfl_sync(FULL, wgt, it);
            int   ki = __shfl_sync(FULL, bidx[rr], it);
            const float* vr = vbase + (size_t)ki * DK_;
            a0 = fmaf(wi, vr[lane],      a0);
            a1 = fmaf(wi, vr[lane + 32], a1);
        }
        float* orow = gx + ((size_t)b * LQ_ + (qt0 + 4*w + rr)) * DM_ + h*DK_;
        orow[lane]      = a0;
        orow[lane + 32] = a1;
    }
}

// ---------------------------------------------------------------------------
extern "C" void kernel_launch(void* const* d_in, const int* in_sizes, int n_in,
                              void* d_out, int out_size)
{
    const float* query = (const float*)d_in[0];
    const float* key   = (const float*)d_in[1];
    const float* value = (const float*)d_in[2];
    const float* Wq    = (const float*)d_in[3];
    const float* bq    = (const float*)d_in[4];
    const float* Wk    = (const float*)d_in[5];
    const float* bk    = (const float*)d_in[6];
    const float* Wv    = (const float*)d_in[7];
    const float* bv    = (const float*)d_in[8];
    const float* Wo    = (const float*)d_in[9];
    const float* bo    = (const float*)d_in[10];
    float* out = (float*)d_out;

    float *pq, *pk, *pv, *px;
    cudaGetSymbolAddress((void**)&pq, g_q);
    cudaGetSymbolAddress((void**)&pk, g_k);
    cudaGetSymbolAddress((void**)&pv, g_v);
    cudaGetSymbolAddress((void**)&px, g_x);

    cudaFuncSetAttribute(attn_topk_kernel,
                         cudaFuncAttributeMaxDynamicSharedMemorySize, SMEM_BYTES);

    // merged Q/K/V projections into head-major scratch
    qkv_gemm_kernel<<<dim3(576, DM_/128), 256>>>(query, key, value,
                                                 Wq, bq, Wk, bk, Wv, bv,
                                                 pq, pk, pv);

    // fused scores + topk + softmax + gather
    attn_topk_kernel<<<dim3(LQ_/QT, H_, B_), 256, SMEM_BYTES>>>(pq, pk, pv, px);

    // output projection (plain row-major)
    out_gemm_kernel<<<dim3(B_*LQ_/128, DM_/128), 256>>>(px, Wo, bo, out);
}